// round 10
// baseline (speedup 1.0000x reference)
#include <cuda_runtime.h>
#include <cuda_fp16.h>
#include <cstdint>

#define D_DIM 256
#define K_DIM 1024
#define N_ROWS 32768

// ---- kernel A (logits+softmax): TM=128 rows/CTA, 512 thr
#define NTHR_A 512
#define XS_STRIDE 264            // halfs/row; A-frag banks 4qr+qc distinct
#define ACH_HALFS (256 * 32)    // chunk: 256 codebook entries x 32 d = 16 KB
#define ACH_BYTES 16384
#define N_ACH 32                 // 4 n-passes x 8 d-chunks

// ---- kernel B (stats+recon): TM=64 rows/CTA, 256 thr
#define NTHR_B 256
#define DS_STRIDE 1032           // halfs/row; A-frag banks 4qr+qc distinct
#define BCH_HALFS (256 * 64)    // chunk: 64 k x 256 d stored [d][64k] = 32 KB
#define BCH_BYTES 32768
#define N_BCH 16

__device__ __align__(16) __half g_chunksA[N_ACH * ACH_HALFS];  // [pass*8+c][k'256][32d rot]
__device__ __align__(16) __half g_chunksB[N_BCH * BCH_HALFS];  // [kc][d 256][64k rot]
__device__ __align__(16) __half g_e[(size_t)N_ROWS * K_DIM];   // raw exp(logits), fp16
__device__ float g_inv[N_ROWS];
__device__ float g_colsum[K_DIM];
__device__ float g_lse_sum;

__device__ __forceinline__ void mma16f(float* c, const uint32_t* a, uint32_t b0, uint32_t b1) {
    asm volatile(
        "mma.sync.aligned.m16n8k16.row.col.f32.f16.f16.f32 "
        "{%0,%1,%2,%3}, {%4,%5,%6,%7}, {%8,%9}, {%0,%1,%2,%3};"
        : "+f"(c[0]), "+f"(c[1]), "+f"(c[2]), "+f"(c[3])
        : "r"(a[0]), "r"(a[1]), "r"(a[2]), "r"(a[3]), "r"(b0), "r"(b1));
}
__device__ __forceinline__ void bulk_cp(uint32_t dst_smem, const void* src,
                                        uint32_t bytes, uint32_t mbar) {
    asm volatile(
        "cp.async.bulk.shared::cta.global.mbarrier::complete_tx::bytes [%0], [%1], %2, [%3];"
        :: "r"(dst_smem), "l"(src), "r"(bytes), "r"(mbar) : "memory");
}
__device__ __forceinline__ void mbar_init(uint32_t mbar, uint32_t cnt) {
    asm volatile("mbarrier.init.shared.b64 [%0], %1;" :: "r"(mbar), "r"(cnt) : "memory");
}
__device__ __forceinline__ void mbar_expect(uint32_t mbar, uint32_t bytes) {
    asm volatile("mbarrier.arrive.expect_tx.shared.b64 _, [%0], %1;"
                 :: "r"(mbar), "r"(bytes) : "memory");
}
__device__ __forceinline__ void mbar_wait(uint32_t mbar, uint32_t parity) {
    asm volatile(
        "{\n\t.reg .pred P;\n\t"
        "WAIT_%=:\n\t"
        "mbarrier.try_wait.parity.acquire.cta.shared::cta.b64 P, [%0], %1, 0x989680;\n\t"
        "@P bra.uni DONE_%=;\n\t"
        "bra.uni WAIT_%=;\n\t"
        "DONE_%=:\n\t}"
        :: "r"(mbar), "r"(parity) : "memory");
}

// ---------------------------------------------------------------------------
// Kernel 1: normalize codebook rows -> fp16, write both rot-swizzled layouts
// ---------------------------------------------------------------------------
__global__ void k_prep(const float* __restrict__ cb) {
    int lane  = threadIdx.x & 31;
    int gwarp = (blockIdx.x * blockDim.x + threadIdx.x) >> 5;
    if (blockIdx.x == 0) {
        for (int k = threadIdx.x; k < K_DIM; k += blockDim.x) g_colsum[k] = 0.0f;
        if (threadIdx.x == 0) g_lse_sum = 0.0f;
    }
    if (gwarp >= K_DIM) return;
    const int k = gwarp;
    const float* row = cb + (size_t)k * D_DIM;
    float v[8]; float ss = 0.0f;
#pragma unroll
    for (int j = 0; j < 8; j++) { v[j] = row[lane + 32 * j]; ss += v[j] * v[j]; }
#pragma unroll
    for (int o = 16; o > 0; o >>= 1) ss += __shfl_xor_sync(0xffffffffu, ss, o);
    float rinv = rsqrtf(ss);
#pragma unroll
    for (int j = 0; j < 8; j++) {
        int d = lane + 32 * j;
        __half h = __float2half_rn(v[j] * rinv);
        // logits layout: rows of 32 halfs (16 words), rotate by ((k&6)<<1)
        int pa = k >> 8, kp = k & 255, ca = d >> 5;
        int wl = (((d & 31) >> 1) + ((k & 6) << 1)) & 15;
        g_chunksA[(size_t)((pa * 8 + ca) * 256 + kp) * 32 + wl * 2 + (d & 1)] = h;
        // recon layout: rows of 64 halfs (32 words), rotate by ((d&7)<<2)
        int kc = k >> 6;
        int wr = (((k & 63) >> 1) + ((d & 7) << 2)) & 31;
        g_chunksB[(size_t)(kc * 256 + d) * 64 + wr * 2 + (k & 1)] = h;
    }
}

// ---------------------------------------------------------------------------
// Kernel A: 128 rows/CTA. normalize -> logits MMA (4 passes of 256 cols)
// -> exp in regs -> store raw e to g_e + rowsum -> g_inv.
// Warp grid per pass: 4m x 4n (warp = 32 rows x 64 cols).
// ---------------------------------------------------------------------------
extern __shared__ __half s_dynA[];

__global__ __launch_bounds__(NTHR_A, 1) void k_main_a(const float* __restrict__ in) {
    __half* xs  = s_dynA;                         // [128][264]
    __half* stg = xs + 128 * XS_STRIDE;           // 2 x 16 KB
    __shared__ __align__(8) unsigned long long s_mbar[2];
    __shared__ float s_rowsum[128];

    const int tid = threadIdx.x;
    const int warp = tid >> 5, lane = tid & 31;
    const int qr = lane >> 2, qc = lane & 3;
    const int wm = warp >> 2, wn = warp & 3;
    const int Rb = 32 * wm;
    const int erow0 = blockIdx.x * 128;
    const size_t base_in = (size_t)blockIdx.x * 128 * D_DIM;

    const uint32_t stg_u32 = (uint32_t)__cvta_generic_to_shared(stg);
    const uint32_t mb0 = (uint32_t)__cvta_generic_to_shared(&s_mbar[0]);
    const uint32_t mb1 = (uint32_t)__cvta_generic_to_shared(&s_mbar[1]);

    if (tid < 128) s_rowsum[tid] = 0.0f;
    if (tid == 0) {
        mbar_init(mb0, 1);
        mbar_init(mb1, 1);
        asm volatile("fence.proxy.async.shared::cta;" ::: "memory");
    }
    __syncthreads();
    if (tid == 0) {
        mbar_expect(mb0, ACH_BYTES);
        bulk_cp(stg_u32, g_chunksA, ACH_BYTES, mb0);
    }

    // load + normalize 8 rows per warp -> fp16 in xs
#pragma unroll
    for (int rr = 0; rr < 8; rr++) {
        int r = warp * 8 + rr;
        const float* rp = in + base_in + (size_t)r * D_DIM;
        float v[8]; float ss = 0.0f;
#pragma unroll
        for (int j = 0; j < 8; j++) { v[j] = rp[lane + 32 * j]; ss += v[j] * v[j]; }
#pragma unroll
        for (int o = 16; o > 0; o >>= 1) ss += __shfl_xor_sync(0xffffffffu, ss, o);
        float rinv = rsqrtf(ss);
#pragma unroll
        for (int j = 0; j < 8; j++)
            xs[r * XS_STRIDE + lane + 32 * j] = __float2half_rn(v[j] * rinv);
    }
    __syncthreads();

    float acc[2][8][4];
    for (int gi = 0; gi < N_ACH; gi++) {
        if ((gi & 7) == 0) {
#pragma unroll
            for (int mt = 0; mt < 2; mt++)
#pragma unroll
                for (int nt = 0; nt < 8; nt++)
#pragma unroll
                    for (int j = 0; j < 4; j++) acc[mt][nt][j] = 0.0f;
        }
        __half* buf = stg + (gi & 1) * ACH_HALFS;
        if (tid == 0 && gi + 1 < N_ACH) {
            uint32_t b = (gi + 1) & 1;
            uint32_t mb = b ? mb1 : mb0;
            mbar_expect(mb, ACH_BYTES);
            bulk_cp(stg_u32 + b * ACH_BYTES,
                    g_chunksA + (size_t)(gi + 1) * ACH_HALFS, ACH_BYTES, mb);
        }
        mbar_wait((gi & 1) ? mb1 : mb0, (gi >> 1) & 1);

        const int dchunk = (gi & 7) * 32;
#pragma unroll
        for (int s = 0; s < 2; s++) {
            uint32_t bv0[8], bv1[8];
#pragma unroll
            for (int nt = 0; nt < 8; nt++) {
                int kp = 64 * wn + 8 * nt + qr;        // codebook entry (n-dim)
                const __half* bp = buf + kp * 32;
                int rot = (kp & 6) << 1;
                bv0[nt] = *(const uint32_t*)(bp + (((8 * s + qc + rot) & 15) << 1));
                bv1[nt] = *(const uint32_t*)(bp + (((8 * s + qc + 4 + rot) & 15) << 1));
            }
#pragma unroll
            for (int mt = 0; mt < 2; mt++) {
                const __half* xr = xs + (Rb + 16 * mt + qr) * XS_STRIDE + dchunk + 16 * s + 2 * qc;
                uint32_t a[4];
                a[0] = *(const uint32_t*)(xr);
                a[1] = *(const uint32_t*)(xr + 8 * XS_STRIDE);
                a[2] = *(const uint32_t*)(xr + 8);
                a[3] = *(const uint32_t*)(xr + 8 * XS_STRIDE + 8);
#pragma unroll
                for (int nt = 0; nt < 8; nt++) mma16f(acc[mt][nt], a, bv0[nt], bv1[nt]);
            }
        }

        if ((gi & 7) == 7) {          // pass end: exp, store raw e, rowsum
            int pass = gi >> 3;
            int colb = 256 * pass + 64 * wn + 2 * qc;
            float pr[4] = {0.0f, 0.0f, 0.0f, 0.0f};
#pragma unroll
            for (int mt = 0; mt < 2; mt++)
#pragma unroll
                for (int nt = 0; nt < 8; nt++) {
                    float e0 = __expf(acc[mt][nt][0]);
                    float e1 = __expf(acc[mt][nt][1]);
                    float e2 = __expf(acc[mt][nt][2]);
                    float e3 = __expf(acc[mt][nt][3]);
                    int r0 = Rb + 16 * mt + qr;
                    int col = colb + 8 * nt;
                    *(__half2*)(g_e + (size_t)(erow0 + r0) * K_DIM + col) =
                        __floats2half2_rn(e0, e1);
                    *(__half2*)(g_e + (size_t)(erow0 + r0 + 8) * K_DIM + col) =
                        __floats2half2_rn(e2, e3);
                    pr[2 * mt]     += e0 + e1;
                    pr[2 * mt + 1] += e2 + e3;
                }
#pragma unroll
            for (int o = 1; o <= 2; o <<= 1)
#pragma unroll
                for (int p4 = 0; p4 < 4; p4++)
                    pr[p4] += __shfl_xor_sync(0xffffffffu, pr[p4], o);
            if (qc == 0) {
                atomicAdd(&s_rowsum[Rb + qr],      pr[0]);
                atomicAdd(&s_rowsum[Rb + 8 + qr],  pr[1]);
                atomicAdd(&s_rowsum[Rb + 16 + qr], pr[2]);
                atomicAdd(&s_rowsum[Rb + 24 + qr], pr[3]);
            }
        }
        __syncthreads();
    }
    if (tid < 128) g_inv[erow0 + tid] = 1.0f / s_rowsum[tid];
}

// ---------------------------------------------------------------------------
// Kernel B: 64 rows/CTA. Load e tile -> stats (colsum, t2/t3 -> lse) ->
// recon MMA streaming codebook -> epilogue scales by inv[row].
// Warp grid: 2m x 4n (warp = 32 rows x 64 cols).
// ---------------------------------------------------------------------------
extern __shared__ __half s_dynB[];

__global__ __launch_bounds__(NTHR_B, 1) void k_main_b(float* __restrict__ out) {
    __half* ds  = s_dynB;                          // [64][1032]
    __half* stg = ds + 64 * DS_STRIDE;             // 2 x 32 KB
    __shared__ __align__(8) unsigned long long s_mbar[2];
    __shared__ float s_inv[64];
    __shared__ float s_lse;

    const int tid = threadIdx.x;
    const int warp = tid >> 5, lane = tid & 31;
    const int qr = lane >> 2, qc = lane & 3;
    const int wm = warp >> 2, wn = warp & 3;
    const int rb = blockIdx.x * 64;

    const uint32_t stg_u32 = (uint32_t)__cvta_generic_to_shared(stg);
    const uint32_t mb0 = (uint32_t)__cvta_generic_to_shared(&s_mbar[0]);
    const uint32_t mb1 = (uint32_t)__cvta_generic_to_shared(&s_mbar[1]);

    if (tid == 0) {
        s_lse = 0.0f;
        mbar_init(mb0, 1);
        mbar_init(mb1, 1);
        asm volatile("fence.proxy.async.shared::cta;" ::: "memory");
    }
    __syncthreads();
    if (tid == 0) {
        mbar_expect(mb0, BCH_BYTES);
        bulk_cp(stg_u32, g_chunksB, BCH_BYTES, mb0);
    }

    // load e tile (64 x 1024 halfs, contiguous in g_e) into padded ds
    {
        const uint4* ep = (const uint4*)(g_e + (size_t)rb * K_DIM);
#pragma unroll
        for (int it = 0; it < 32; it++) {
            int idx = it * NTHR_B + tid;
            int r = idx >> 7, c8 = (idx & 127) * 8;
            uint4 v = ep[idx];
            *(uint4*)(ds + r * DS_STRIDE + c8) = v;
        }
    }
    if (tid < 64) s_inv[tid] = g_inv[rb + tid];
    __syncthreads();

    // ---- colsum: thread owns half2 col-pairs tid, tid+256
#pragma unroll
    for (int jj = 0; jj < 2; jj++) {
        int cp = tid + 256 * jj;
        float s0 = 0.0f, s1 = 0.0f;
#pragma unroll 8
        for (int r = 0; r < 64; r++) {
            float2 f = __half22float2(*(const __half2*)(ds + r * DS_STRIDE + 2 * cp));
            float iv = s_inv[r];
            s0 += f.x * iv; s1 += f.y * iv;
        }
        atomicAdd(&g_colsum[2 * cp], s0);
        atomicAdd(&g_colsum[2 * cp + 1], s1);
    }
    // ---- t2/t3 + lse: 4 threads per row
    {
        int r = tid >> 2, seg = tid & 3;
        float iv = s_inv[r];
        float t2 = 0.0f, t3 = 0.0f;
        const __half* row = ds + r * DS_STRIDE;
#pragma unroll 8
        for (int j = 0; j < 128; j++) {
            float2 f = __half22float2(*(const __half2*)(row + 2 * (seg + 4 * j)));
            float d0 = f.x * iv, d1 = f.y * iv;
            t2 += d0 * d0 + d1 * d1;
            t3 += d0 * d0 * d0 + d1 * d1 * d1;
        }
#pragma unroll
        for (int o = 1; o <= 2; o <<= 1) {
            t2 += __shfl_xor_sync(0xffffffffu, t2, o);
            t3 += __shfl_xor_sync(0xffffffffu, t3, o);
        }
        if (seg == 0)
            atomicAdd(&s_lse, __logf(1025.0f + 0.5f * t2 + 0.16666667f * t3));
    }
    __syncthreads();
    if (tid == 0) atomicAdd(&g_lse_sum, s_lse);

    // ---- recon MMA: 16 chunks of 64 k
    float acc[2][8][4];
#pragma unroll
    for (int mt = 0; mt < 2; mt++)
#pragma unroll
        for (int nt = 0; nt < 8; nt++)
#pragma unroll
            for (int j = 0; j < 4; j++) acc[mt][nt][j] = 0.0f;

    for (int gi = 0; gi < N_BCH; gi++) {
        __half* buf = stg + (gi & 1) * BCH_HALFS;
        if (tid == 0 && gi + 1 < N_BCH) {
            uint32_t b = (gi + 1) & 1;
            uint32_t mb = b ? mb1 : mb0;
            mbar_expect(mb, BCH_BYTES);
            bulk_cp(stg_u32 + b * BCH_BYTES,
                    g_chunksB + (size_t)(gi + 1) * BCH_HALFS, BCH_BYTES, mb);
        }
        mbar_wait((gi & 1) ? mb1 : mb0, (gi >> 1) & 1);

#pragma unroll
        for (int ks = 0; ks < 4; ks++) {
            uint32_t bv0[8], bv1[8];
#pragma unroll
            for (int nt = 0; nt < 8; nt++) {
                int d = 64 * wn + 8 * nt + qr;         // output col (n-dim)
                const __half* bp = buf + d * 64;
                int rot = qr << 2;                      // (d&7)<<2 == qr<<2
                bv0[nt] = *(const uint32_t*)(bp + (((8 * ks + qc + rot) & 31) << 1));
                bv1[nt] = *(const uint32_t*)(bp + (((8 * ks + qc + 4 + rot) & 31) << 1));
            }
#pragma unroll
            for (int mt = 0; mt < 2; mt++) {
                const __half* dr = ds + (32 * wm + 16 * mt + qr) * DS_STRIDE
                                   + gi * 64 + ks * 16 + 2 * qc;
                uint32_t a[4];
                a[0] = *(const uint32_t*)(dr);
                a[1] = *(const uint32_t*)(dr + 8 * DS_STRIDE);
                a[2] = *(const uint32_t*)(dr + 8);
                a[3] = *(const uint32_t*)(dr + 8 * DS_STRIDE + 8);
#pragma unroll
                for (int nt = 0; nt < 8; nt++) mma16f(acc[mt][nt], a, bv0[nt], bv1[nt]);
            }
        }
        __syncthreads();
    }

    // ---- epilogue: scale by inv[row], write out
#pragma unroll
    for (int mt = 0; mt < 2; mt++)
#pragma unroll
        for (int nt = 0; nt < 8; nt++) {
            int r0 = 32 * wm + 16 * mt + qr;
            int col = 64 * wn + 8 * nt + 2 * qc;
            float iv0 = s_inv[r0], iv1 = s_inv[r0 + 8];
            *reinterpret_cast<float2*>(out + (size_t)(rb + r0) * D_DIM + col) =
                make_float2(acc[mt][nt][0] * iv0, acc[mt][nt][1] * iv0);
            *reinterpret_cast<float2*>(out + (size_t)(rb + r0 + 8) * D_DIM + col) =
                make_float2(acc[mt][nt][2] * iv1, acc[mt][nt][3] * iv1);
        }
}

// ---------------------------------------------------------------------------
// Kernel 4: finalize loss.  l1 == 1/K exactly.
// entropy = sum_i lse_i - ||colsum||^2 / N
// ---------------------------------------------------------------------------
__global__ void k_loss(float* __restrict__ out, int out_size) {
    __shared__ float red[8];
    int tid = threadIdx.x;
    float s = 0.0f;
    for (int k = tid; k < K_DIM; k += 256) { float c = g_colsum[k]; s += c * c; }
#pragma unroll
    for (int o = 16; o > 0; o >>= 1) s += __shfl_xor_sync(0xffffffffu, s, o);
    if ((tid & 31) == 0) red[tid >> 5] = s;
    __syncthreads();
    if (tid == 0) {
        float t = 0.0f;
#pragma unroll
        for (int w = 0; w < 8; w++) t += red[w];
        float entropy = g_lse_sum - t / (float)N_ROWS;
        float loss = 1000.0f * (1.0f / (float)K_DIM) + 5e-5f * entropy;
        out[out_size - 1] = loss;
    }
}

extern "C" void kernel_launch(void* const* d_in, const int* in_sizes, int n_in,
                              void* d_out, int out_size) {
    const float* in = (const float*)d_in[0];
    const float* cb = (const float*)d_in[1];
    float* out = (float*)d_out;
    (void)in_sizes; (void)n_in;

    const size_t smemA = (size_t)(128 * XS_STRIDE + 2 * ACH_HALFS) * sizeof(__half);
    const size_t smemB = (size_t)(64 * DS_STRIDE + 2 * BCH_HALFS) * sizeof(__half);
    cudaFuncSetAttribute(k_main_a, cudaFuncAttributeMaxDynamicSharedMemorySize, (int)smemA);
    cudaFuncSetAttribute(k_main_b, cudaFuncAttributeMaxDynamicSharedMemorySize, (int)smemB);

    k_prep<<<K_DIM / 8, 256>>>(cb);
    k_main_a<<<N_ROWS / 128, NTHR_A, smemA>>>(in);
    k_main_b<<<N_ROWS / 64, NTHR_B, smemB>>>(out);
    k_loss<<<1, 256>>>(out, out_size);
}

// round 11
// speedup vs baseline: 1.1028x; 1.1028x over previous
#include <cuda_runtime.h>
#include <cuda_fp16.h>
#include <cstdint>

#define D_DIM 256
#define K_DIM 1024
#define N_ROWS 32768
#define TM 64
#define NTHR 512
#define XS_STRIDE 264
#define DS_STRIDE 1032
#define CH_HALFS 16384      // 32 KB chunks
#define CH_BYTES 32768

__device__ __align__(16) __half g_chunksA[16 * CH_HALFS];  // [pass*8+dc][e 512][32d rot]
__device__ __align__(16) __half g_chunksB[16 * CH_HALFS];  // [kc][d 256][64k rot]
__device__ float g_colsum[K_DIM];
__device__ float g_lse_sum;

__device__ __forceinline__ void mma16f(float* c, const uint32_t* a, uint32_t b0, uint32_t b1) {
    asm volatile(
        "mma.sync.aligned.m16n8k16.row.col.f32.f16.f16.f32 "
        "{%0,%1,%2,%3}, {%4,%5,%6,%7}, {%8,%9}, {%0,%1,%2,%3};"
        : "+f"(c[0]), "+f"(c[1]), "+f"(c[2]), "+f"(c[3])
        : "r"(a[0]), "r"(a[1]), "r"(a[2]), "r"(a[3]), "r"(b0), "r"(b1));
}
__device__ __forceinline__ void bulk_cp(uint32_t d, const void* s, uint32_t b, uint32_t m) {
    asm volatile("cp.async.bulk.shared::cta.global.mbarrier::complete_tx::bytes [%0], [%1], %2, [%3];"
                 :: "r"(d), "l"(s), "r"(b), "r"(m) : "memory");
}
__device__ __forceinline__ void mbar_init(uint32_t m, uint32_t c) {
    asm volatile("mbarrier.init.shared.b64 [%0], %1;" :: "r"(m), "r"(c) : "memory");
}
__device__ __forceinline__ void mbar_expect(uint32_t m, uint32_t b) {
    asm volatile("mbarrier.arrive.expect_tx.shared.b64 _, [%0], %1;" :: "r"(m), "r"(b) : "memory");
}
__device__ __forceinline__ void mbar_wait(uint32_t m, uint32_t p) {
    asm volatile("{\n\t.reg .pred P;\n\tW_%=: mbarrier.try_wait.parity.acquire.cta.shared::cta.b64 P, [%0], %1, 0x989680;\n\t@P bra.uni D_%=;\n\tbra.uni W_%=;\n\tD_%=:\n\t}"
                 :: "r"(m), "r"(p) : "memory");
}

__global__ void k_prep(const float* __restrict__ cb) {
    int lane = threadIdx.x & 31;
    int gw = (blockIdx.x * blockDim.x + threadIdx.x) >> 5;
    if (blockIdx.x == 0) {
        for (int k = threadIdx.x; k < K_DIM; k += blockDim.x) g_colsum[k] = 0.0f;
        if (threadIdx.x == 0) g_lse_sum = 0.0f;
    }
    if (gw >= K_DIM) return;
    const int k = gw;
    const float* row = cb + (size_t)k * D_DIM;
    float v[8]; float ss = 0.0f;
#pragma unroll
    for (int j = 0; j < 8; j++) { v[j] = row[lane + 32 * j]; ss += v[j] * v[j]; }
#pragma unroll
    for (int o = 16; o > 0; o >>= 1) ss += __shfl_xor_sync(0xffffffffu, ss, o);
    float rinv = rsqrtf(ss);
#pragma unroll
    for (int j = 0; j < 8; j++) {
        int d = lane + 32 * j;
        __half h = __float2half_rn(v[j] * rinv);
        int pa = k >> 9, e = k & 511, ca = d >> 5;
        int wl = (((d & 31) >> 1) + ((k & 6) << 1)) & 15;
        g_chunksA[(size_t)((pa * 8 + ca) * 512 + e) * 32 + wl * 2 + (d & 1)] = h;
        int kc = k >> 6;
        int wr = (((k & 63) >> 1) + ((d & 7) << 2)) & 31;
        g_chunksB[(size_t)(kc * 256 + d) * 64 + wr * 2 + (k & 1)] = h;
    }
}

extern __shared__ __half s_h[];

__global__ __launch_bounds__(NTHR, 1) void k_main(const float* __restrict__ in,
                                                  float* __restrict__ out) {
    __half* xs  = s_h;                         // [64][264]
    __half* ds  = xs + TM * XS_STRIDE;         // [64][1032] raw e
    __half* stg = ds + TM * DS_STRIDE;         // 2 x 32 KB
    __shared__ __align__(8) unsigned long long s_mbar[2];
    __shared__ float s_rs[TM], s_inv[TM], s_lse;

    const int tid = threadIdx.x;
    const int warp = tid >> 5, lane = tid & 31;
    const int qr = lane >> 2, qc = lane & 3;
    const int wm = warp >> 3, wn = warp & 7;   // 2m x 8n
    const int Rb = 32 * wm;
    const int rb = blockIdx.x * TM;

    const uint32_t stg_a = (uint32_t)__cvta_generic_to_shared(stg);
    const uint32_t mb0 = (uint32_t)__cvta_generic_to_shared(&s_mbar[0]);
    const uint32_t mb1 = (uint32_t)__cvta_generic_to_shared(&s_mbar[1]);

    if (tid < TM) s_rs[tid] = 0.0f;
    if (tid == 0) {
        s_lse = 0.0f;
        mbar_init(mb0, 1); mbar_init(mb1, 1);
        asm volatile("fence.proxy.async.shared::cta;" ::: "memory");
    }
    __syncthreads();
    if (tid == 0) { mbar_expect(mb0, CH_BYTES); bulk_cp(stg_a, g_chunksA, CH_BYTES, mb0); }

    // normalize 4 rows/warp -> fp16
#pragma unroll
    for (int rr = 0; rr < 4; rr++) {
        int r = warp * 4 + rr;
        const float* rp = in + (size_t)(rb + r) * D_DIM;
        float v[8]; float ss = 0.0f;
#pragma unroll
        for (int j = 0; j < 8; j++) { v[j] = rp[lane + 32 * j]; ss += v[j] * v[j]; }
#pragma unroll
        for (int o = 16; o > 0; o >>= 1) ss += __shfl_xor_sync(0xffffffffu, ss, o);
        float rinv = rsqrtf(ss);
#pragma unroll
        for (int j = 0; j < 8; j++)
            xs[r * XS_STRIDE + lane + 32 * j] = __float2half_rn(v[j] * rinv);
    }
    __syncthreads();

    // ---- logits: 2 n-passes x 8 d-chunks.  warp owns 64 cols per pass.
    float acc[2][8][4];
    const int rot = (qr & 6) << 1;
    for (int gi = 0; gi < 16; gi++) {
        if ((gi & 7) == 0)
#pragma unroll
            for (int mt = 0; mt < 2; mt++)
#pragma unroll
                for (int nt = 0; nt < 8; nt++)
#pragma unroll
                    for (int j = 0; j < 4; j++) acc[mt][nt][j] = 0.0f;
        __half* buf = stg + (gi & 1) * CH_HALFS;
        if (tid == 0 && gi + 1 < 16) {
            uint32_t b = (gi + 1) & 1, mb = b ? mb1 : mb0;
            mbar_expect(mb, CH_BYTES);
            bulk_cp(stg_a + b * CH_BYTES, g_chunksA + (size_t)(gi + 1) * CH_HALFS, CH_BYTES, mb);
        }
        mbar_wait((gi & 1) ? mb1 : mb0, (gi >> 1) & 1);

        const int dchunk = (gi & 7) * 32;
#pragma unroll
        for (int s = 0; s < 2; s++) {
            uint32_t bv0[8], bv1[8];
#pragma unroll
            for (int nt = 0; nt < 8; nt++) {
                const __half* bp = buf + (64 * wn + 8 * nt + qr) * 32;
                bv0[nt] = *(const uint32_t*)(bp + (((8 * s + qc + rot) & 15) << 1));
                bv1[nt] = *(const uint32_t*)(bp + (((8 * s + qc + 4 + rot) & 15) << 1));
            }
#pragma unroll
            for (int mt = 0; mt < 2; mt++) {
                const __half* xr = xs + (Rb + 16 * mt + qr) * XS_STRIDE + dchunk + 16 * s + 2 * qc;
                uint32_t a[4];
                a[0] = *(const uint32_t*)(xr);
                a[1] = *(const uint32_t*)(xr + 8 * XS_STRIDE);
                a[2] = *(const uint32_t*)(xr + 8);
                a[3] = *(const uint32_t*)(xr + 8 * XS_STRIDE + 8);
#pragma unroll
                for (int nt = 0; nt < 8; nt++) mma16f(acc[mt][nt], a, bv0[nt], bv1[nt]);
            }
        }

        if ((gi & 7) == 7) {   // pass end: exp -> raw e to ds + row partial sums
            int colb = 512 * (gi >> 3) + 64 * wn + 2 * qc;
            float pr[4] = {0, 0, 0, 0};
#pragma unroll
            for (int mt = 0; mt < 2; mt++)
#pragma unroll
                for (int nt = 0; nt < 8; nt++) {
                    float e0 = __expf(acc[mt][nt][0]);
                    float e1 = __expf(acc[mt][nt][1]);
                    float e2 = __expf(acc[mt][nt][2]);
                    float e3 = __expf(acc[mt][nt][3]);
                    int r0 = Rb + 16 * mt + qr, col = colb + 8 * nt;
                    *(__half2*)(ds + r0 * DS_STRIDE + col)       = __floats2half2_rn(e0, e1);
                    *(__half2*)(ds + (r0 + 8) * DS_STRIDE + col) = __floats2half2_rn(e2, e3);
                    pr[2 * mt] += e0 + e1; pr[2 * mt + 1] += e2 + e3;
                }
#pragma unroll
            for (int o = 1; o <= 2; o <<= 1)
#pragma unroll
                for (int p = 0; p < 4; p++) pr[p] += __shfl_xor_sync(0xffffffffu, pr[p], o);
            if (qc == 0) {
                atomicAdd(&s_rs[Rb + qr],      pr[0]);
                atomicAdd(&s_rs[Rb + 8 + qr],  pr[1]);
                atomicAdd(&s_rs[Rb + 16 + qr], pr[2]);
                atomicAdd(&s_rs[Rb + 24 + qr], pr[3]);
            }
        }
        __syncthreads();
    }
    if (tid == 0) { mbar_expect(mb0, CH_BYTES); bulk_cp(stg_a, g_chunksB, CH_BYTES, mb0); }
    if (tid < TM) s_inv[tid] = 1.0f / s_rs[tid];
    __syncthreads();

    // ---- colsum (thread owns half2 pair tid)
    {
        float s0 = 0.0f, s1 = 0.0f;
#pragma unroll 8
        for (int r = 0; r < TM; r++) {
            float2 f = __half22float2(*(const __half2*)(ds + r * DS_STRIDE + 2 * tid));
            float iv = s_inv[r];
            s0 += f.x * iv; s1 += f.y * iv;
        }
        atomicAdd(&g_colsum[2 * tid], s0);
        atomicAdd(&g_colsum[2 * tid + 1], s1);
    }
    // ---- t2/t3 + lse (8 threads/row)
    {
        int r = tid >> 3, seg = tid & 7;
        float iv = s_inv[r];
        float t2 = 0.0f, t3 = 0.0f;
        const __half* row = ds + r * DS_STRIDE;
#pragma unroll 8
        for (int j = 0; j < 64; j++) {
            float2 f = __half22float2(*(const __half2*)(row + 2 * (seg + 8 * j)));
            float d0 = f.x * iv, d1 = f.y * iv;
            t2 += d0 * d0 + d1 * d1;
            t3 += d0 * d0 * d0 + d1 * d1 * d1;
        }
#pragma unroll
        for (int o = 1; o <= 4; o <<= 1) {
            t2 += __shfl_xor_sync(0xffffffffu, t2, o);
            t3 += __shfl_xor_sync(0xffffffffu, t3, o);
        }
        if (seg == 0) atomicAdd(&s_lse, __logf(1025.0f + 0.5f * t2 + 0.16666667f * t3));
    }
    __syncthreads();
    if (tid == 0) atomicAdd(&g_lse_sum, s_lse);

    // ---- recon: 16 chunks of 64 k.  warp owns 32 cols.
    float ac2[2][4][4];
#pragma unroll
    for (int mt = 0; mt < 2; mt++)
#pragma unroll
        for (int nt = 0; nt < 4; nt++)
#pragma unroll
            for (int j = 0; j < 4; j++) ac2[mt][nt][j] = 0.0f;
    const int rotR = qr << 2;
    for (int gi = 0; gi < 16; gi++) {
        __half* buf = stg + (gi & 1) * CH_HALFS;
        if (tid == 0 && gi + 1 < 16) {
            uint32_t b = (gi + 1) & 1, mb = b ? mb1 : mb0;
            mbar_expect(mb, CH_BYTES);
            bulk_cp(stg_a + b * CH_BYTES, g_chunksB + (size_t)(gi + 1) * CH_HALFS, CH_BYTES, mb);
        }
        mbar_wait((gi & 1) ? mb1 : mb0, (gi >> 1) & 1);

#pragma unroll
        for (int ks = 0; ks < 4; ks++) {
            uint32_t bv0[4], bv1[4];
#pragma unroll
            for (int nt = 0; nt < 4; nt++) {
                const __half* bp = buf + (32 * wn + 8 * nt + qr) * 64;
                bv0[nt] = *(const uint32_t*)(bp + (((8 * ks + qc + rotR) & 31) << 1));
                bv1[nt] = *(const uint32_t*)(bp + (((8 * ks + qc + 4 + rotR) & 31) << 1));
            }
#pragma unroll
            for (int mt = 0; mt < 2; mt++) {
                const __half* dr = ds + (Rb + 16 * mt + qr) * DS_STRIDE + gi * 64 + ks * 16 + 2 * qc;
                uint32_t a[4];
                a[0] = *(const uint32_t*)(dr);
                a[1] = *(const uint32_t*)(dr + 8 * DS_STRIDE);
                a[2] = *(const uint32_t*)(dr + 8);
                a[3] = *(const uint32_t*)(dr + 8 * DS_STRIDE + 8);
#pragma unroll
                for (int nt = 0; nt < 4; nt++) mma16f(ac2[mt][nt], a, bv0[nt], bv1[nt]);
            }
        }
        __syncthreads();
    }

    // ---- epilogue: scale by inv[row]
#pragma unroll
    for (int mt = 0; mt < 2; mt++)
#pragma unroll
        for (int nt = 0; nt < 4; nt++) {
            int r0 = Rb + 16 * mt + qr;
            int col = 32 * wn + 8 * nt + 2 * qc;
            float iv0 = s_inv[r0], iv1 = s_inv[r0 + 8];
            *reinterpret_cast<float2*>(out + (size_t)(rb + r0) * D_DIM + col) =
                make_float2(ac2[mt][nt][0] * iv0, ac2[mt][nt][1] * iv0);
            *reinterpret_cast<float2*>(out + (size_t)(rb + r0 + 8) * D_DIM + col) =
                make_float2(ac2[mt][nt][2] * iv1, ac2[mt][nt][3] * iv1);
        }
}

__global__ void k_loss(float* __restrict__ out, int out_size) {
    __shared__ float red[8];
    int tid = threadIdx.x;
    float s = 0.0f;
    for (int k = tid; k < K_DIM; k += 256) { float c = g_colsum[k]; s += c * c; }
#pragma unroll
    for (int o = 16; o > 0; o >>= 1) s += __shfl_xor_sync(0xffffffffu, s, o);
    if ((tid & 31) == 0) red[tid >> 5] = s;
    __syncthreads();
    if (tid == 0) {
        float t = 0.0f;
#pragma unroll
        for (int w = 0; w < 8; w++) t += red[w];
        float entropy = g_lse_sum - t / (float)N_ROWS;
        out[out_size - 1] = 1000.0f * (1.0f / (float)K_DIM) + 5e-5f * entropy;
    }
}

extern "C" void kernel_launch(void* const* d_in, const int* in_sizes, int n_in,
                              void* d_out, int out_size) {
    const float* in = (const float*)d_in[0];
    const float* cb = (const float*)d_in[1];
    float* out = (float*)d_out;
    (void)in_sizes; (void)n_in;
    const size_t smem = (size_t)(TM * XS_STRIDE + TM * DS_STRIDE + 2 * CH_HALFS) * sizeof(__half);
    cudaFuncSetAttribute(k_main, cudaFuncAttributeMaxDynamicSharedMemorySize, (int)smem);
    k_prep<<<K_DIM / 8, 256>>>(cb);
    k_main<<<N_ROWS / TM, NTHR, smem>>>(in, out);
    k_loss<<<1, 256>>>(out, out_size);
}